// round 16
// baseline (speedup 1.0000x reference)
#include <cuda_runtime.h>
#include <cuda.h>
#include <cuda_bf16.h>
#include <math.h>
#include <stdint.h>

// ---------------- problem constants ----------------
#define TOKENS   8192
#define DMODEL   1024
#define NEXP     8
#define DFFN     2048
#define TOPK     2

#define BM 128
#define BN 128                          // CTA tile N
#define CAP (TOKENS*TOPK + NEXP*BM)    // 17408
#define ROW_TILES (CAP/BM)             // 136

#define BK 32                           // k elements per stage chunk
#define APLANE 8192                     // 128 rows x 64B (swizzled, no padding)
#define BPLANE 8192
#define STAGE_BYTES (2*APLANE + 2*BPLANE)   // 32768
#define NSTAGE 3
#define SMEM_SZ (NSTAGE*STAGE_BYTES + 1024) // 99328 -> 2 CTAs/SM

// ---------------- device scratch (bf16 hi/lo planes) ----------------
__device__ __align__(1024) __nv_bfloat16 g_x_hi[(size_t)TOKENS * DMODEL];   // per token
__device__ __align__(1024) __nv_bfloat16 g_x_lo[(size_t)TOKENS * DMODEL];
__device__ __align__(1024) __nv_bfloat16 g_h_hi[(size_t)CAP * DFFN];
__device__ __align__(1024) __nv_bfloat16 g_h_lo[(size_t)CAP * DFFN];
__device__ __align__(1024) __nv_bfloat16 g_w1t_hi[(size_t)NEXP * DFFN * DMODEL];
__device__ __align__(1024) __nv_bfloat16 g_w1t_lo[(size_t)NEXP * DFFN * DMODEL];
__device__ __align__(1024) __nv_bfloat16 g_w2t_hi[(size_t)NEXP * DMODEL * DFFN];
__device__ __align__(1024) __nv_bfloat16 g_w2t_lo[(size_t)NEXP * DMODEL * DFFN];
__device__ __align__(1024) float g_y[(size_t)CAP * DMODEL];
__device__ float g_pair_w[CAP];
__device__ int   g_pair_tok[CAP];
__device__ int   g_tok2row[TOKENS * TOPK];
__device__ int   g_counts[2 * NEXP];    // [0..7]=cnt, [8..15]=cursor
__device__ float g_probs[TOKENS * NEXP];
__device__ float g_zsq[TOKENS];
__device__ int   g_sel[TOKENS * TOPK];
__device__ float g_selw[TOKENS * TOPK];

// ---------------- helpers ----------------
__device__ __forceinline__ uint32_t smem_u32(const void* p) {
    uint32_t a;
    asm("{ .reg .u64 t; cvta.to.shared.u64 t, %1; cvt.u32.u64 %0, t; }" : "=r"(a) : "l"(p));
    return a;
}

__device__ __forceinline__ void mma_bf16(float* c, const uint32_t* a, const uint32_t* b) {
    asm volatile(
        "mma.sync.aligned.m16n8k16.row.col.f32.bf16.bf16.f32 "
        "{%0,%1,%2,%3}, {%4,%5,%6,%7}, {%8,%9}, {%0,%1,%2,%3};"
        : "+f"(c[0]), "+f"(c[1]), "+f"(c[2]), "+f"(c[3])
        : "r"(a[0]), "r"(a[1]), "r"(a[2]), "r"(a[3]), "r"(b[0]), "r"(b[1]));
}

__device__ __forceinline__ void ldsm_x4(uint32_t& r0, uint32_t& r1, uint32_t& r2, uint32_t& r3,
                                        uint32_t addr) {
    asm volatile("ldmatrix.sync.aligned.m8n8.x4.shared.b16 {%0,%1,%2,%3}, [%4];"
        : "=r"(r0), "=r"(r1), "=r"(r2), "=r"(r3) : "r"(addr));
}

#define CP_ASYNC16(saddr, gaddr) \
    asm volatile("cp.async.cg.shared.global [%0], [%1], 16;" :: "r"(saddr), "l"(gaddr) : "memory")
#define CP_ASYNC16_ZF(saddr, gaddr, n) \
    asm volatile("cp.async.cg.shared.global [%0], [%1], 16, %2;" \
        :: "r"(saddr), "l"(gaddr), "r"(n) : "memory")
#define CP_COMMIT() asm volatile("cp.async.commit_group;" ::: "memory")
#define CP_WAIT1()  asm volatile("cp.async.wait_group 1;" ::: "memory")

__device__ __forceinline__ float gelu_exact(float u) {
    return 0.5f * u * (1.0f + erff(u * 0.70710678118654752440f));
}

__device__ __forceinline__ void calc_off(int* off) {
    int o = 0;
#pragma unroll
    for (int e = 0; e < NEXP; e++) {
        off[e] = o;
        o += ((g_counts[e] + BM - 1) / BM) * BM;
    }
    off[NEXP] = o;
}

// ---------------- router: warp per token ----------------
__global__ __launch_bounds__(256) void router_kernel(const float* __restrict__ x,
                                                     const float* __restrict__ rw) {
    __shared__ float srw[NEXP * DMODEL];
    int tid = threadIdx.x;
    for (int i = tid; i < NEXP * DMODEL; i += 256) srw[i] = rw[i];
    __syncthreads();

    int warp = tid >> 5, lane = tid & 31;
    int tok = blockIdx.x * 8 + warp;
    if (tok >= TOKENS) return;

    const float* xr = x + (size_t)tok * DMODEL;
    float acc[NEXP];
#pragma unroll
    for (int e = 0; e < NEXP; e++) acc[e] = 0.f;
    for (int i = lane; i < DMODEL; i += 32) {
        float xv = xr[i];
#pragma unroll
        for (int e = 0; e < NEXP; e++) acc[e] += xv * srw[e * DMODEL + i];
    }
#pragma unroll
    for (int off = 16; off; off >>= 1)
#pragma unroll
        for (int e = 0; e < NEXP; e++)
            acc[e] += __shfl_down_sync(0xffffffffu, acc[e], off);

    if (lane == 0) {
        float m = acc[0];
#pragma unroll
        for (int e = 1; e < NEXP; e++) m = fmaxf(m, acc[e]);
        float p[NEXP], s = 0.f;
#pragma unroll
        for (int e = 0; e < NEXP; e++) { p[e] = expf(acc[e] - m); s += p[e]; }
        float inv = 1.f / s;
#pragma unroll
        for (int e = 0; e < NEXP; e++) { p[e] *= inv; g_probs[tok * NEXP + e] = p[e]; }
        float lse = logf(s) + m;
        g_zsq[tok] = lse * lse;

        int e1 = 0;
#pragma unroll
        for (int e = 1; e < NEXP; e++) if (p[e] > p[e1]) e1 = e;
        int e2 = (e1 == 0) ? 1 : 0;
#pragma unroll
        for (int e = 0; e < NEXP; e++) if (e != e1 && p[e] > p[e2]) e2 = e;

        float wsum = p[e1] + p[e2];
        g_sel[tok * 2 + 0] = e1;  g_selw[tok * 2 + 0] = p[e1] / wsum;
        g_sel[tok * 2 + 1] = e2;  g_selw[tok * 2 + 1] = p[e2] / wsum;
        atomicAdd(&g_counts[e1], 1);
        atomicAdd(&g_counts[e2], 1);
    }
}

// fused scatter + per-token gather/split (single copy)
__global__ __launch_bounds__(128) void scatter_gather(const float* __restrict__ x) {
    int t = blockIdx.x;
    if (threadIdx.x == 0) {
        int off[NEXP + 1];
        calc_off(off);
#pragma unroll
        for (int k = 0; k < TOPK; k++) {
            int e = g_sel[t * 2 + k];
            int pos = off[e] + atomicAdd(&g_counts[NEXP + e], 1);
            g_pair_w[pos] = g_selw[t * 2 + k];
            g_pair_tok[pos] = t;
            g_tok2row[t * 2 + k] = pos;
        }
    }
    const float2* src = (const float2*)(x + (size_t)t * DMODEL);
    __nv_bfloat162* dh = (__nv_bfloat162*)(g_x_hi + (size_t)t * DMODEL);
    __nv_bfloat162* dl = (__nv_bfloat162*)(g_x_lo + (size_t)t * DMODEL);
    for (int i = threadIdx.x; i < DMODEL / 2; i += 128) {
        float2 v = src[i];
        __nv_bfloat162 h = __floats2bfloat162_rn(v.x, v.y);
        float2 hf = __bfloat1622float2(h);
        dh[i] = h;
        dl[i] = __floats2bfloat162_rn(v.x - hf.x, v.y - hf.y);
    }
}

// w1 [1024][16384] -> planes [(e,n)][k]
__global__ __launch_bounds__(256) void transpose_w1_split(const float* __restrict__ in) {
    __shared__ float t[32][33];
    int c0 = blockIdx.x * 32, r0 = blockIdx.y * 32;
    int x = threadIdx.x, y = threadIdx.y;
#pragma unroll
    for (int i = 0; i < 32; i += 8) t[y + i][x] = in[(size_t)(r0 + y + i) * 16384 + c0 + x];
    __syncthreads();
#pragma unroll
    for (int i = 0; i < 32; i += 8) {
        float v = t[x][y + i];
        size_t idx = (size_t)(c0 + y + i) * 1024 + r0 + x;
        __nv_bfloat16 h = __float2bfloat16(v);
        g_w1t_hi[idx] = h;
        g_w1t_lo[idx] = __float2bfloat16(v - __bfloat162float(h));
    }
}

// w2 [e][2048][1024] -> planes [(e,n)][k]
__global__ __launch_bounds__(256) void transpose_w2_split(const float* __restrict__ in) {
    __shared__ float t[32][33];
    int e = blockIdx.z;
    int n0 = blockIdx.x * 32, k0 = blockIdx.y * 32;
    int x = threadIdx.x, y = threadIdx.y;
#pragma unroll
    for (int i = 0; i < 32; i += 8)
        t[y + i][x] = in[((size_t)e * 2048 + k0 + y + i) * 1024 + n0 + x];
    __syncthreads();
#pragma unroll
    for (int i = 0; i < 32; i += 8) {
        float v = t[x][y + i];
        size_t idx = ((size_t)e * 1024 + n0 + y + i) * 2048 + k0 + x;
        __nv_bfloat16 h = __float2bfloat16(v);
        g_w2t_hi[idx] = h;
        g_w2t_lo[idx] = __float2bfloat16(v - __bfloat162float(h));
    }
}

// ===== GEMM: 128x128 tile, 256 thr, 2 CTAs/SM, 3-stage swizzled smem, 1 bar/chunk =====
// FFN1: A rows gathered on the fly via smem token table + cp.async zfill for pads.
template <bool FFN1>
__global__ __launch_bounds__(256, 2) void gemm_bf16(const __nv_bfloat16* __restrict__ Ah,
                                                    const __nv_bfloat16* __restrict__ Al,
                                                    const __nv_bfloat16* __restrict__ Bh,
                                                    const __nv_bfloat16* __restrict__ Bl) {
    const int KDIM = FFN1 ? DMODEL : DFFN;
    const int NCH  = KDIM / BK;

    int off[NEXP + 1];
    calc_off(off);

    int row0 = blockIdx.y * BM;
    if (row0 >= off[NEXP]) return;
    int e = 0;
#pragma unroll
    for (int i = 0; i < NEXP; i++) if (row0 >= off[i + 1]) e = i + 1;

    const int n0 = blockIdx.x * BN;
    const int ybase = (FFN1 ? e * DFFN : e * DMODEL) + n0;
    int tid = threadIdx.x, wid = tid >> 5, lane = tid & 31;
    int wr = wid >> 2, wc = wid & 3;            // 2x4 warp grid; warp tile 64x32
    int gid = lane >> 2, tig = lane & 3;

    extern __shared__ char smem[];
    uint32_t sbase = smem_u32(smem);
    float* swt = (float*)(smem + NSTAGE * STAGE_BYTES);
    int* stok  = (int*)(smem + NSTAGE * STAGE_BYTES + 512);
    if (FFN1) {
        if (tid < BM) {
            bool valid = (row0 + tid) < (off[e] + g_counts[e]);
            stok[tid] = valid ? g_pair_tok[row0 + tid] : -1;
        }
    } else {
        if (tid < BM) swt[tid] = g_pair_w[row0 + tid];
    }
    __syncthreads();   // stok visible before prologue fills

    // ldmatrix lane addressing with XOR swizzle (invariant under +16-row steps)
    int sel = lane >> 3, lr = lane & 7;
    int ra0 = wr * 64 + (sel & 1) * 8 + lr;
    int rb0 = wc * 32 + (sel >> 1) * 8 + lr;
    int xa = (sel >> 1) ^ ((ra0 >> 1) & 3);
    int xb = (sel & 1)  ^ ((rb0 >> 1) & 3);
    uint32_t abase = (uint32_t)(ra0 * 64);
    uint32_t bbase = (uint32_t)(rb0 * 64);

    float c[4][4][4];
#pragma unroll
    for (int i = 0; i < 4; i++)
#pragma unroll
        for (int j = 0; j < 4; j++)
#pragma unroll
            for (int q = 0; q < 4; q++) c[i][j][q] = 0.f;

    // one quarter of a stage fill (512 x 16B): 2 cp.async per thread
    auto fill_q = [&](int st, int kc, int qq) {
        uint32_t base = sbase + st * STAGE_BYTES;
        int k0 = kc * BK;
#pragma unroll
        for (int it = 0; it < 2; it++) {
            int q = tid + 256 * (qq * 2 + it);
            int plane = q >> 9;                  // 0=Ahi 1=Alo 2=Bhi 3=Blo
            int rr = (q >> 2) & 127;
            int cc = q & 3;
            uint32_t dst = base + plane * 8192 + rr * 64 + (((cc ^ ((rr >> 1) & 3))) << 4);
            if (FFN1 && plane < 2) {
                int tok = stok[rr];
                const __nv_bfloat16* src = (plane ? Al : Ah)
                    + (size_t)(tok < 0 ? 0 : tok) * KDIM + k0 + cc * 8;
                CP_ASYNC16_ZF(dst, src, tok < 0 ? 0 : 16);
            } else {
                const __nv_bfloat16* src;
                if      (plane == 0) src = Ah + (size_t)(row0 + rr) * KDIM + k0 + cc * 8;
                else if (plane == 1) src = Al + (size_t)(row0 + rr) * KDIM + k0 + cc * 8;
                else if (plane == 2) src = Bh + (size_t)(ybase + rr) * KDIM + k0 + cc * 8;
                else                 src = Bl + (size_t)(ybase + rr) * KDIM + k0 + cc * 8;
                CP_ASYNC16(dst, src);
            }
        }
    };

#pragma unroll
    for (int qq = 0; qq < 4; qq++) fill_q(0, 0, qq);
    CP_COMMIT();
#pragma unroll
    for (int qq = 0; qq < 4; qq++) fill_q(1, 1, qq);
    CP_COMMIT();

    for (int kc = 0; kc < NCH; kc++) {
        CP_WAIT1();
        __syncthreads();                         // single barrier per chunk
        bool do_fill = (kc + 2 < NCH);
        int fst = (kc + 2) % NSTAGE;

        uint32_t stg = sbase + (kc % NSTAGE) * STAGE_BYTES;
#pragma unroll
        for (int kk = 0; kk < 2; kk++) {
            uint32_t achunk = (uint32_t)((xa ^ (kk << 1)) << 4);
            uint32_t bchunk = (uint32_t)((xb ^ (kk << 1)) << 4);
            uint32_t ah[4][4], al[4][4], bh[4][2], bl[4][2];

            // load hi fragments first (6 LDSM) -> hh pass can start early
#pragma unroll
            for (int i = 0; i < 4; i++) {
                uint32_t a_addr = stg + abase + i * 1024 + achunk;
                ldsm_x4(ah[i][0], ah[i][1], ah[i][2], ah[i][3], a_addr);
            }
#pragma unroll
            for (int jp = 0; jp < 2; jp++) {
                uint32_t b_addr = stg + 2 * APLANE + bbase + jp * 1024 + bchunk;
                ldsm_x4(bh[jp * 2][0], bh[jp * 2][1], bh[jp * 2 + 1][0], bh[jp * 2 + 1][1], b_addr);
            }
            if (do_fill) { fill_q(fst, kc + 2, kk * 2); }
#pragma unroll
            for (int i = 0; i < 4; i++)
#pragma unroll
                for (int j = 0; j < 4; j++) mma_bf16(c[i][j], ah[i], bh[j]);   // hh

            // load A-lo under the hh pass tail, run lh
#pragma unroll
            for (int i = 0; i < 4; i++) {
                uint32_t a_addr = stg + abase + i * 1024 + achunk + APLANE;
                ldsm_x4(al[i][0], al[i][1], al[i][2], al[i][3], a_addr);
            }
            if (do_fill) {
                fill_q(fst, kc + 2, kk * 2 + 1);
                if (kk == 1) CP_COMMIT();
            }
#pragma unroll
            for (int i = 0; i < 4; i++)
#pragma unroll
                for (int j = 0; j < 4; j++) mma_bf16(c[i][j], al[i], bh[j]);   // lh

            // load B-lo under the lh pass, run hl
#pragma unroll
            for (int jp = 0; jp < 2; jp++) {
                uint32_t b_addr = stg + 2 * APLANE + bbase + jp * 1024 + bchunk + BPLANE;
                ldsm_x4(bl[jp * 2][0], bl[jp * 2][1], bl[jp * 2 + 1][0], bl[jp * 2 + 1][1], b_addr);
            }
#pragma unroll
            for (int i = 0; i < 4; i++)
#pragma unroll
                for (int j = 0; j < 4; j++) mma_bf16(c[i][j], ah[i], bl[j]);   // hl
        }
    }

    // epilogue
#pragma unroll
    for (int i = 0; i < 4; i++) {
        int mr0 = wr * 64 + i * 16 + gid;
        int mr1 = mr0 + 8;
        if (FFN1) {
#pragma unroll
            for (int j = 0; j < 4; j++) {
                int col = wc * 32 + j * 8 + tig * 2;
                float u0 = gelu_exact(c[i][j][0]), u1 = gelu_exact(c[i][j][1]);
                float u2 = gelu_exact(c[i][j][2]), u3 = gelu_exact(c[i][j][3]);
                size_t i0 = (size_t)(row0 + mr0) * DFFN + n0 + col;
                size_t i1 = (size_t)(row0 + mr1) * DFFN + n0 + col;
                __nv_bfloat162 h0 = __floats2bfloat162_rn(u0, u1);
                float2 f0 = __bfloat1622float2(h0);
                *(__nv_bfloat162*)(g_h_hi + i0) = h0;
                *(__nv_bfloat162*)(g_h_lo + i0) = __floats2bfloat162_rn(u0 - f0.x, u1 - f0.y);
                __nv_bfloat162 h1 = __floats2bfloat162_rn(u2, u3);
                float2 f1 = __bfloat1622float2(h1);
                *(__nv_bfloat162*)(g_h_hi + i1) = h1;
                *(__nv_bfloat162*)(g_h_lo + i1) = __floats2bfloat162_rn(u2 - f1.x, u3 - f1.y);
            }
        } else {
            float ws0 = swt[mr0], ws1 = swt[mr1];
            float* y0 = g_y + (size_t)(row0 + mr0) * DMODEL + n0;
            float* y1 = g_y + (size_t)(row0 + mr1) * DMODEL + n0;
#pragma unroll
            for (int j = 0; j < 4; j++) {
                int col = wc * 32 + j * 8 + tig * 2;
                *(float2*)(y0 + col) = make_float2(ws0 * c[i][j][0], ws0 * c[i][j][1]);
                *(float2*)(y1 + col) = make_float2(ws1 * c[i][j][2], ws1 * c[i][j][3]);
            }
        }
    }
}

// ---------------- combine ----------------
__global__ __launch_bounds__(128) void combine_kernel(float* __restrict__ out) {
    int t = blockIdx.x;
    int ra = g_tok2row[t * 2 + 0];
    int rb = g_tok2row[t * 2 + 1];
    const float4* ya = (const float4*)(g_y + (size_t)ra * DMODEL);
    const float4* yb = (const float4*)(g_y + (size_t)rb * DMODEL);
    float4* o = (float4*)(out + (size_t)t * DMODEL);
    for (int i = threadIdx.x; i < DMODEL / 4; i += 128) {
        float4 a = ya[i], b = yb[i];
        o[i] = make_float4(a.x + b.x, a.y + b.y, a.z + b.z, a.w + b.w);
    }
}

// ---------------- aux losses ----------------
__global__ __launch_bounds__(256) void reduce_kernel(float* __restrict__ out, int out_size) {
    __shared__ float sbuf[256];
    int tid = threadIdx.x;

    float z = 0.f;
    for (int t = tid; t < TOKENS; t += 256) z += g_zsq[t];
    sbuf[tid] = z; __syncthreads();
    for (int s = 128; s; s >>= 1) { if (tid < s) sbuf[tid] += sbuf[tid + s]; __syncthreads(); }
    float zloss = sbuf[0] / (float)TOKENS;
    __syncthreads();

    float p[NEXP];
#pragma unroll
    for (int e = 0; e < NEXP; e++) p[e] = 0.f;
    for (int t = tid; t < TOKENS; t += 256) {
#pragma unroll
        for (int e = 0; e < NEXP; e++) p[e] += g_probs[t * NEXP + e];
    }
    float pi[NEXP];
#pragma unroll
    for (int e = 0; e < NEXP; e++) {
        sbuf[tid] = p[e]; __syncthreads();
        for (int s = 128; s; s >>= 1) { if (tid < s) sbuf[tid] += sbuf[tid + s]; __syncthreads(); }
        pi[e] = sbuf[0] / (float)TOKENS;
        __syncthreads();
    }

    if (tid == 0 && out_size >= TOKENS * DMODEL + 2 + NEXP) {
        float* tail = out + (size_t)TOKENS * DMODEL;
        tail[0] = zloss;
        float lb = 0.f;
#pragma unroll
        for (int e = 0; e < NEXP; e++) {
            float fi = (float)g_counts[e] / (float)(TOKENS * TOPK);
            lb += fi * pi[e];
            tail[2 + e] = fi;
        }
        tail[1] = (float)NEXP * lb;
    }
}

// ---------------- host ----------------
extern "C" void kernel_launch(void* const* d_in, const int* in_sizes, int n_in,
                              void* d_out, int out_size) {
    const float* x  = (const float*)d_in[0];
    const float* rw = (const float*)d_in[1];
    const float* w1 = (const float*)d_in[2];
    const float* w2 = (const float*)d_in[3];
    float* out = (float*)d_out;

    void *p_counts;
    void *p_xh, *p_xl, *p_hh, *p_hl, *p_w1h, *p_w1l, *p_w2h, *p_w2l;
    cudaGetSymbolAddress(&p_counts, g_counts);
    cudaGetSymbolAddress(&p_xh,  g_x_hi);
    cudaGetSymbolAddress(&p_xl,  g_x_lo);
    cudaGetSymbolAddress(&p_hh,  g_h_hi);
    cudaGetSymbolAddress(&p_hl,  g_h_lo);
    cudaGetSymbolAddress(&p_w1h, g_w1t_hi);
    cudaGetSymbolAddress(&p_w1l, g_w1t_lo);
    cudaGetSymbolAddress(&p_w2h, g_w2t_hi);
    cudaGetSymbolAddress(&p_w2l, g_w2t_lo);

    cudaFuncSetAttribute(gemm_bf16<true>,  cudaFuncAttributeMaxDynamicSharedMemorySize, SMEM_SZ);
    cudaFuncSetAttribute(gemm_bf16<false>, cudaFuncAttributeMaxDynamicSharedMemorySize, SMEM_SZ);

    // one-time side streams + events (no device allocations)
    static cudaStream_t s1 = nullptr, s2 = nullptr;
    static cudaEvent_t evRoot = nullptr, ev1 = nullptr, ev2 = nullptr;
    static cudaEvent_t evRouter = nullptr, evReduce = nullptr;
    if (!s1) {
        cudaStreamCreateWithFlags(&s1, cudaStreamNonBlocking);
        cudaStreamCreateWithFlags(&s2, cudaStreamNonBlocking);
        cudaEventCreateWithFlags(&evRoot,   cudaEventDisableTiming);
        cudaEventCreateWithFlags(&ev1,      cudaEventDisableTiming);
        cudaEventCreateWithFlags(&ev2,      cudaEventDisableTiming);
        cudaEventCreateWithFlags(&evRouter, cudaEventDisableTiming);
        cudaEventCreateWithFlags(&evReduce, cudaEventDisableTiming);
    }

    cudaMemsetAsync(p_counts, 0, 2 * NEXP * sizeof(int));

    // fork: transposes on side streams, concurrent with router/scatter
    cudaEventRecord(evRoot, 0);
    cudaStreamWaitEvent(s1, evRoot, 0);
    cudaStreamWaitEvent(s2, evRoot, 0);
    transpose_w1_split<<<dim3(16384 / 32, 1024 / 32), dim3(32, 8), 0, s1>>>(w1);
    cudaEventRecord(ev1, s1);
    transpose_w2_split<<<dim3(1024 / 32, 2048 / 32, NEXP), dim3(32, 8), 0, s2>>>(w2);
    cudaEventRecord(ev2, s2);

    // main chain
    router_kernel<<<TOKENS / 8, 256>>>(x, rw);
    cudaEventRecord(evRouter, 0);
    scatter_gather<<<TOKENS, 128>>>(x);

    // aux-loss reduction concurrent with GEMMs (depends only on router)
    cudaStreamWaitEvent(s1, evRouter, 0);
    reduce_kernel<<<1, 256, 0, s1>>>(out, out_size);
    cudaEventRecord(evReduce, s1);

    cudaStreamWaitEvent(0, ev1, 0);   // gemm1 needs w1 planes
    gemm_bf16<true><<<dim3(DFFN / BN, ROW_TILES), 256, SMEM_SZ>>>(
        (const __nv_bfloat16*)p_xh, (const __nv_bfloat16*)p_xl,
        (const __nv_bfloat16*)p_w1h, (const __nv_bfloat16*)p_w1l);

    cudaStreamWaitEvent(0, ev2, 0);   // gemm2 needs w2 planes
    gemm_bf16<false><<<dim3(DMODEL / BN, ROW_TILES), 256, SMEM_SZ>>>(
        (const __nv_bfloat16*)p_hh, (const __nv_bfloat16*)p_hl,
        (const __nv_bfloat16*)p_w2h, (const __nv_bfloat16*)p_w2l);

    combine_kernel<<<TOKENS, 128>>>(out);
    cudaStreamWaitEvent(0, evReduce, 0);   // join: reduce wrote the out tail
}

// round 17
// speedup vs baseline: 1.0668x; 1.0668x over previous
#include <cuda_runtime.h>
#include <cuda.h>
#include <cuda_bf16.h>
#include <math.h>
#include <stdint.h>

// ---------------- problem constants ----------------
#define TOKENS   8192
#define DMODEL   1024
#define NEXP     8
#define DFFN     2048
#define TOPK     2

#define BM 128
#define BN 128                          // CTA tile N
#define CAP (TOKENS*TOPK + NEXP*BM)    // 17408
#define ROW_TILES (CAP/BM)             // 136

#define BK 32                           // k elements per stage chunk
#define APLANE 8192                     // 128 rows x 64B (swizzled, no padding)
#define BPLANE 8192
#define STAGE_BYTES (2*APLANE + 2*BPLANE)   // 32768
#define NSTAGE 3
#define SMEM_SZ (NSTAGE*STAGE_BYTES + 512)  // 98816 -> 2 CTAs/SM

// ---------------- device scratch (bf16 hi/lo planes) ----------------
__device__ __align__(1024) __nv_bfloat16 g_xg_hi[(size_t)CAP * DMODEL];
__device__ __align__(1024) __nv_bfloat16 g_xg_lo[(size_t)CAP * DMODEL];
__device__ __align__(1024) __nv_bfloat16 g_h_hi[(size_t)CAP * DFFN];
__device__ __align__(1024) __nv_bfloat16 g_h_lo[(size_t)CAP * DFFN];
__device__ __align__(1024) __nv_bfloat16 g_w1t_hi[(size_t)NEXP * DFFN * DMODEL];
__device__ __align__(1024) __nv_bfloat16 g_w1t_lo[(size_t)NEXP * DFFN * DMODEL];
__device__ __align__(1024) __nv_bfloat16 g_w2t_hi[(size_t)NEXP * DMODEL * DFFN];
__device__ __align__(1024) __nv_bfloat16 g_w2t_lo[(size_t)NEXP * DMODEL * DFFN];
__device__ __align__(1024) float g_y[(size_t)CAP * DMODEL];
__device__ float g_pair_w[CAP];
__device__ int   g_tok2row[TOKENS * TOPK];
__device__ int   g_counts[2 * NEXP];    // [0..7]=cnt, [8..15]=cursor
__device__ float g_probs[TOKENS * NEXP];
__device__ float g_zsq[TOKENS];
__device__ int   g_sel[TOKENS * TOPK];
__device__ float g_selw[TOKENS * TOPK];

// ---------------- helpers ----------------
__device__ __forceinline__ uint32_t smem_u32(const void* p) {
    uint32_t a;
    asm("{ .reg .u64 t; cvta.to.shared.u64 t, %1; cvt.u32.u64 %0, t; }" : "=r"(a) : "l"(p));
    return a;
}

__device__ __forceinline__ void mma_bf16(float* c, const uint32_t* a, const uint32_t* b) {
    asm volatile(
        "mma.sync.aligned.m16n8k16.row.col.f32.bf16.bf16.f32 "
        "{%0,%1,%2,%3}, {%4,%5,%6,%7}, {%8,%9}, {%0,%1,%2,%3};"
        : "+f"(c[0]), "+f"(c[1]), "+f"(c[2]), "+f"(c[3])
        : "r"(a[0]), "r"(a[1]), "r"(a[2]), "r"(a[3]), "r"(b[0]), "r"(b[1]));
}

__device__ __forceinline__ void ldsm_x4(uint32_t& r0, uint32_t& r1, uint32_t& r2, uint32_t& r3,
                                        uint32_t addr) {
    asm volatile("ldmatrix.sync.aligned.m8n8.x4.shared.b16 {%0,%1,%2,%3}, [%4];"
        : "=r"(r0), "=r"(r1), "=r"(r2), "=r"(r3) : "r"(addr));
}

#define CP_ASYNC16(saddr, gaddr) \
    asm volatile("cp.async.cg.shared.global [%0], [%1], 16;" :: "r"(saddr), "l"(gaddr) : "memory")
#define CP_COMMIT() asm volatile("cp.async.commit_group;" ::: "memory")
#define CP_WAIT1()  asm volatile("cp.async.wait_group 1;" ::: "memory")

__device__ __forceinline__ float gelu_exact(float u) {
    return 0.5f * u * (1.0f + erff(u * 0.70710678118654752440f));
}

__device__ __forceinline__ void calc_off(int* off) {
    int o = 0;
#pragma unroll
    for (int e = 0; e < NEXP; e++) {
        off[e] = o;
        o += ((g_counts[e] + BM - 1) / BM) * BM;
    }
    off[NEXP] = o;
}

// ---------------- router: warp per token ----------------
__global__ __launch_bounds__(256) void router_kernel(const float* __restrict__ x,
                                                     const float* __restrict__ rw) {
    __shared__ float srw[NEXP * DMODEL];
    int tid = threadIdx.x;
    for (int i = tid; i < NEXP * DMODEL; i += 256) srw[i] = rw[i];
    __syncthreads();

    int warp = tid >> 5, lane = tid & 31;
    int tok = blockIdx.x * 8 + warp;
    if (tok >= TOKENS) return;

    const float* xr = x + (size_t)tok * DMODEL;
    float acc[NEXP];
#pragma unroll
    for (int e = 0; e < NEXP; e++) acc[e] = 0.f;
    for (int i = lane; i < DMODEL; i += 32) {
        float xv = xr[i];
#pragma unroll
        for (int e = 0; e < NEXP; e++) acc[e] += xv * srw[e * DMODEL + i];
    }
#pragma unroll
    for (int off = 16; off; off >>= 1)
#pragma unroll
        for (int e = 0; e < NEXP; e++)
            acc[e] += __shfl_down_sync(0xffffffffu, acc[e], off);

    if (lane == 0) {
        float m = acc[0];
#pragma unroll
        for (int e = 1; e < NEXP; e++) m = fmaxf(m, acc[e]);
        float p[NEXP], s = 0.f;
#pragma unroll
        for (int e = 0; e < NEXP; e++) { p[e] = expf(acc[e] - m); s += p[e]; }
        float inv = 1.f / s;
#pragma unroll
        for (int e = 0; e < NEXP; e++) { p[e] *= inv; g_probs[tok * NEXP + e] = p[e]; }
        float lse = logf(s) + m;
        g_zsq[tok] = lse * lse;

        int e1 = 0;
#pragma unroll
        for (int e = 1; e < NEXP; e++) if (p[e] > p[e1]) e1 = e;
        int e2 = (e1 == 0) ? 1 : 0;
#pragma unroll
        for (int e = 0; e < NEXP; e++) if (e != e1 && p[e] > p[e2]) e2 = e;

        float wsum = p[e1] + p[e2];
        g_sel[tok * 2 + 0] = e1;  g_selw[tok * 2 + 0] = p[e1] / wsum;
        g_sel[tok * 2 + 1] = e2;  g_selw[tok * 2 + 1] = p[e2] / wsum;
        atomicAdd(&g_counts[e1], 1);
        atomicAdd(&g_counts[e2], 1);
    }
}

// fused scatter + gather/split: block per token (duplicated pair-row planes)
__global__ __launch_bounds__(128) void scatter_gather(const float* __restrict__ x) {
    __shared__ int spos[2];
    int t = blockIdx.x;
    if (threadIdx.x == 0) {
        int off[NEXP + 1];
        calc_off(off);
#pragma unroll
        for (int k = 0; k < TOPK; k++) {
            int e = g_sel[t * 2 + k];
            int pos = off[e] + atomicAdd(&g_counts[NEXP + e], 1);
            g_pair_w[pos] = g_selw[t * 2 + k];
            g_tok2row[t * 2 + k] = pos;
            spos[k] = pos;
        }
    }
    __syncthreads();
    int p0 = spos[0], p1 = spos[1];
    const float2* src = (const float2*)(x + (size_t)t * DMODEL);
    __nv_bfloat162* dh0 = (__nv_bfloat162*)(g_xg_hi + (size_t)p0 * DMODEL);
    __nv_bfloat162* dl0 = (__nv_bfloat162*)(g_xg_lo + (size_t)p0 * DMODEL);
    __nv_bfloat162* dh1 = (__nv_bfloat162*)(g_xg_hi + (size_t)p1 * DMODEL);
    __nv_bfloat162* dl1 = (__nv_bfloat162*)(g_xg_lo + (size_t)p1 * DMODEL);
    for (int i = threadIdx.x; i < DMODEL / 2; i += 128) {
        float2 v = src[i];
        __nv_bfloat162 h = __floats2bfloat162_rn(v.x, v.y);
        float2 hf = __bfloat1622float2(h);
        __nv_bfloat162 l = __floats2bfloat162_rn(v.x - hf.x, v.y - hf.y);
        dh0[i] = h; dl0[i] = l;
        dh1[i] = h; dl1[i] = l;
    }
}

// w1 [1024][16384] -> planes [(e,n)][k]
__global__ __launch_bounds__(256) void transpose_w1_split(const float* __restrict__ in) {
    __shared__ float t[32][33];
    int c0 = blockIdx.x * 32, r0 = blockIdx.y * 32;
    int x = threadIdx.x, y = threadIdx.y;
#pragma unroll
    for (int i = 0; i < 32; i += 8) t[y + i][x] = in[(size_t)(r0 + y + i) * 16384 + c0 + x];
    __syncthreads();
#pragma unroll
    for (int i = 0; i < 32; i += 8) {
        float v = t[x][y + i];
        size_t idx = (size_t)(c0 + y + i) * 1024 + r0 + x;
        __nv_bfloat16 h = __float2bfloat16(v);
        g_w1t_hi[idx] = h;
        g_w1t_lo[idx] = __float2bfloat16(v - __bfloat162float(h));
    }
}

// w2 [e][2048][1024] -> planes [(e,n)][k]
__global__ __launch_bounds__(256) void transpose_w2_split(const float* __restrict__ in) {
    __shared__ float t[32][33];
    int e = blockIdx.z;
    int n0 = blockIdx.x * 32, k0 = blockIdx.y * 32;
    int x = threadIdx.x, y = threadIdx.y;
#pragma unroll
    for (int i = 0; i < 32; i += 8)
        t[y + i][x] = in[((size_t)e * 2048 + k0 + y + i) * 1024 + n0 + x];
    __syncthreads();
#pragma unroll
    for (int i = 0; i < 32; i += 8) {
        float v = t[x][y + i];
        size_t idx = ((size_t)e * 1024 + n0 + y + i) * 2048 + k0 + x;
        __nv_bfloat16 h = __float2bfloat16(v);
        g_w2t_hi[idx] = h;
        g_w2t_lo[idx] = __float2bfloat16(v - __bfloat162float(h));
    }
}

// ===== GEMM: 128x128 tile, 256 thr, 2 CTAs/SM, 3-stage swizzled smem, 1 bar/chunk =====
// staggered passes: hh starts after 6 LDSM; lo-plane loads + fill bursts hide under mma.
template <bool FFN1>
__global__ __launch_bounds__(256, 2) void gemm_bf16(const __nv_bfloat16* __restrict__ Ah,
                                                    const __nv_bfloat16* __restrict__ Al,
                                                    const __nv_bfloat16* __restrict__ Bh,
                                                    const __nv_bfloat16* __restrict__ Bl) {
    const int KDIM = FFN1 ? DMODEL : DFFN;
    const int NCH  = KDIM / BK;

    int off[NEXP + 1];
    calc_off(off);

    int row0 = blockIdx.y * BM;
    if (row0 >= off[NEXP]) return;
    int e = 0;
#pragma unroll
    for (int i = 0; i < NEXP; i++) if (row0 >= off[i + 1]) e = i + 1;

    const int n0 = blockIdx.x * BN;
    const int ybase = (FFN1 ? e * DFFN : e * DMODEL) + n0;
    int tid = threadIdx.x, wid = tid >> 5, lane = tid & 31;
    int wr = wid >> 2, wc = wid & 3;            // 2x4 warp grid; warp tile 64x32
    int gid = lane >> 2, tig = lane & 3;

    extern __shared__ char smem[];
    uint32_t sbase = smem_u32(smem);
    float* swt = (float*)(smem + NSTAGE * STAGE_BYTES);
    if (!FFN1 && tid < BM) swt[tid] = g_pair_w[row0 + tid];

    // ldmatrix lane addressing with XOR swizzle (invariant under +16-row steps)
    int sel = lane >> 3, lr = lane & 7;
    int ra0 = wr * 64 + (sel & 1) * 8 + lr;
    int rb0 = wc * 32 + (sel >> 1) * 8 + lr;
    int xa = (sel >> 1) ^ ((ra0 >> 1) & 3);
    int xb = (sel & 1)  ^ ((rb0 >> 1) & 3);
    uint32_t abase = (uint32_t)(ra0 * 64);
    uint32_t bbase = (uint32_t)(rb0 * 64);

    float c[4][4][4];
#pragma unroll
    for (int i = 0; i < 4; i++)
#pragma unroll
        for (int j = 0; j < 4; j++)
#pragma unroll
            for (int q = 0; q < 4; q++) c[i][j][q] = 0.f;

    // one quarter of a stage fill (512 x 16B): 2 cp.async per thread
    auto fill_q = [&](int st, int kc, int qq) {
        uint32_t base = sbase + st * STAGE_BYTES;
        int k0 = kc * BK;
#pragma unroll
        for (int it = 0; it < 2; it++) {
            int q = tid + 256 * (qq * 2 + it);
            int plane = q >> 9;                  // 0=Ahi 1=Alo 2=Bhi 3=Blo
            int rr = (q >> 2) & 127;
            int cc = q & 3;
            uint32_t dst = base + plane * 8192 + rr * 64 + (((cc ^ ((rr >> 1) & 3))) << 4);
            const __nv_bfloat16* src;
            if      (plane == 0) src = Ah + (size_t)(row0 + rr) * KDIM + k0 + cc * 8;
            else if (plane == 1) src = Al + (size_t)(row0 + rr) * KDIM + k0 + cc * 8;
            else if (plane == 2) src = Bh + (size_t)(ybase + rr) * KDIM + k0 + cc * 8;
            else                 src = Bl + (size_t)(ybase + rr) * KDIM + k0 + cc * 8;
            CP_ASYNC16(dst, src);
        }
    };

#pragma unroll
    for (int qq = 0; qq < 4; qq++) fill_q(0, 0, qq);
    CP_COMMIT();
#pragma unroll
    for (int qq = 0; qq < 4; qq++) fill_q(1, 1, qq);
    CP_COMMIT();

    for (int kc = 0; kc < NCH; kc++) {
        CP_WAIT1();
        __syncthreads();                         // single barrier per chunk
        bool do_fill = (kc + 2 < NCH);
        int fst = (kc + 2) % NSTAGE;

        uint32_t stg = sbase + (kc % NSTAGE) * STAGE_BYTES;
#pragma unroll
        for (int kk = 0; kk < 2; kk++) {
            uint32_t achunk = (uint32_t)((xa ^ (kk << 1)) << 4);
            uint32_t bchunk = (uint32_t)((xb ^ (kk << 1)) << 4);
            uint32_t ah[4][4], al[4][4], bh[4][2], bl[4][2];

            // load hi fragments first (6 LDSM) -> hh pass can start early
#pragma unroll
            for (int i = 0; i < 4; i++) {
                uint32_t a_addr = stg + abase + i * 1024 + achunk;
                ldsm_x4(ah[i][0], ah[i][1], ah[i][2], ah[i][3], a_addr);
            }
#pragma unroll
            for (int jp = 0; jp < 2; jp++) {
                uint32_t b_addr = stg + 2 * APLANE + bbase + jp * 1024 + bchunk;
                ldsm_x4(bh[jp * 2][0], bh[jp * 2][1], bh[jp * 2 + 1][0], bh[jp * 2 + 1][1], b_addr);
            }
            if (kk == 0 && do_fill) { fill_q(fst, kc + 2, 0); fill_q(fst, kc + 2, 1); }
#pragma unroll
            for (int i = 0; i < 4; i++)
#pragma unroll
                for (int j = 0; j < 4; j++) mma_bf16(c[i][j], ah[i], bh[j]);   // hh

            // load A-lo under the hh pass tail, run lh
#pragma unroll
            for (int i = 0; i < 4; i++) {
                uint32_t a_addr = stg + abase + i * 1024 + achunk + APLANE;
                ldsm_x4(al[i][0], al[i][1], al[i][2], al[i][3], a_addr);
            }
            if (kk == 0 && do_fill) { fill_q(fst, kc + 2, 2); fill_q(fst, kc + 2, 3); CP_COMMIT(); }
#pragma unroll
            for (int i = 0; i < 4; i++)
#pragma unroll
                for (int j = 0; j < 4; j++) mma_bf16(c[i][j], al[i], bh[j]);   // lh

            // load B-lo under the lh pass, run hl
#pragma unroll
            for (int jp = 0; jp < 2; jp++) {
                uint32_t b_addr = stg + 2 * APLANE + bbase + jp * 1024 + bchunk + BPLANE;
                ldsm_x4(bl[jp * 2][0], bl[jp * 2][1], bl[jp * 2 + 1][0], bl[jp * 2 + 1][1], b_addr);
            }
#pragma unroll
            for (int i = 0; i < 4; i++)
#pragma unroll
                for (int j = 0; j < 4; j++) mma_bf16(c[i][j], ah[i], bl[j]);   // hl
        }
    }

    // epilogue
#pragma unroll
    for (int i = 0; i < 4; i++) {
        int mr0 = wr * 64 + i * 16 + gid;
        int mr1 = mr0 + 8;
        if (FFN1) {
#pragma unroll
            for (int j = 0; j < 4; j++) {
                int col = wc * 32 + j * 8 + tig * 2;
                float u0 = gelu_exact(c[i][j][0]), u1 = gelu_exact(c[i][j][1]);
                float u2 = gelu_exact(c[i][j][2]), u3 = gelu_exact(c[i][j][3]);
                size_t i0 = (size_t)(row0 + mr0) * DFFN + n0 + col;
                size_t i1 = (size_t)(row0 + mr1) * DFFN + n0 + col;
                __nv_bfloat162 h0 = __floats2bfloat162_rn(u0, u1);
                float2 f0 = __bfloat1622float2(h0);
                *(__nv_bfloat162*)(g_h_hi + i0) = h0;
                *(__nv_bfloat162*)(g_h_lo + i0) = __floats2bfloat162_rn(u0 - f0.x, u1 - f0.y);
                __nv_bfloat162 h1 = __floats2bfloat162_rn(u2, u3);
                float2 f1 = __bfloat1622float2(h1);
                *(__nv_bfloat162*)(g_h_hi + i1) = h1;
                *(__nv_bfloat162*)(g_h_lo + i1) = __floats2bfloat162_rn(u2 - f1.x, u3 - f1.y);
            }
        } else {
            float ws0 = swt[mr0], ws1 = swt[mr1];
            float* y0 = g_y + (size_t)(row0 + mr0) * DMODEL + n0;
            float* y1 = g_y + (size_t)(row0 + mr1) * DMODEL + n0;
#pragma unroll
            for (int j = 0; j < 4; j++) {
                int col = wc * 32 + j * 8 + tig * 2;
                *(float2*)(y0 + col) = make_float2(ws0 * c[i][j][0], ws0 * c[i][j][1]);
                *(float2*)(y1 + col) = make_float2(ws1 * c[i][j][2], ws1 * c[i][j][3]);
            }
        }
    }
}

// ---------------- combine ----------------
__global__ __launch_bounds__(128) void combine_kernel(float* __restrict__ out) {
    int t = blockIdx.x;
    int ra = g_tok2row[t * 2 + 0];
    int rb = g_tok2row[t * 2 + 1];
    const float4* ya = (const float4*)(g_y + (size_t)ra * DMODEL);
    const float4* yb = (const float4*)(g_y + (size_t)rb * DMODEL);
    float4* o = (float4*)(out + (size_t)t * DMODEL);
    for (int i = threadIdx.x; i < DMODEL / 4; i += 128) {
        float4 a = ya[i], b = yb[i];
        o[i] = make_float4(a.x + b.x, a.y + b.y, a.z + b.z, a.w + b.w);
    }
}

// ---------------- aux losses ----------------
__global__ __launch_bounds__(256) void reduce_kernel(float* __restrict__ out, int out_size) {
    __shared__ float sbuf[256];
    int tid = threadIdx.x;

    float z = 0.f;
    for (int t = tid; t < TOKENS; t += 256) z += g_zsq[t];
    sbuf[tid] = z; __syncthreads();
    for (int s = 128; s; s >>= 1) { if (tid < s) sbuf[tid] += sbuf[tid + s]; __syncthreads(); }
    float zloss = sbuf[0] / (float)TOKENS;
    __syncthreads();

    float p[NEXP];
#pragma unroll
    for (int e = 0; e < NEXP; e++) p[e] = 0.f;
    for (int t = tid; t < TOKENS; t += 256) {
#pragma unroll
        for (int e = 0; e < NEXP; e++) p[e] += g_probs[t * NEXP + e];
    }
    float pi[NEXP];
#pragma unroll
    for (int e = 0; e < NEXP; e++) {
        sbuf[tid] = p[e]; __syncthreads();
        for (int s = 128; s; s >>= 1) { if (tid < s) sbuf[tid] += sbuf[tid + s]; __syncthreads(); }
        pi[e] = sbuf[0] / (float)TOKENS;
        __syncthreads();
    }

    if (tid == 0 && out_size >= TOKENS * DMODEL + 2 + NEXP) {
        float* tail = out + (size_t)TOKENS * DMODEL;
        tail[0] = zloss;
        float lb = 0.f;
#pragma unroll
        for (int e = 0; e < NEXP; e++) {
            float fi = (float)g_counts[e] / (float)(TOKENS * TOPK);
            lb += fi * pi[e];
            tail[2 + e] = fi;
        }
        tail[1] = (float)NEXP * lb;
    }
}

// ---------------- host ----------------
extern "C" void kernel_launch(void* const* d_in, const int* in_sizes, int n_in,
                              void* d_out, int out_size) {
    const float* x  = (const float*)d_in[0];
    const float* rw = (const float*)d_in[1];
    const float* w1 = (const float*)d_in[2];
    const float* w2 = (const float*)d_in[3];
    float* out = (float*)d_out;

    void *p_counts;
    void *p_xh, *p_xl, *p_hh, *p_hl, *p_w1h, *p_w1l, *p_w2h, *p_w2l;
    cudaGetSymbolAddress(&p_counts, g_counts);
    cudaGetSymbolAddress(&p_xh,  g_xg_hi);
    cudaGetSymbolAddress(&p_xl,  g_xg_lo);
    cudaGetSymbolAddress(&p_hh,  g_h_hi);
    cudaGetSymbolAddress(&p_hl,  g_h_lo);
    cudaGetSymbolAddress(&p_w1h, g_w1t_hi);
    cudaGetSymbolAddress(&p_w1l, g_w1t_lo);
    cudaGetSymbolAddress(&p_w2h, g_w2t_hi);
    cudaGetSymbolAddress(&p_w2l, g_w2t_lo);

    cudaFuncSetAttribute(gemm_bf16<true>,  cudaFuncAttributeMaxDynamicSharedMemorySize, SMEM_SZ);
    cudaFuncSetAttribute(gemm_bf16<false>, cudaFuncAttributeMaxDynamicSharedMemorySize, SMEM_SZ);

    // one-time side streams + events (no device allocations)
    static cudaStream_t s1 = nullptr, s2 = nullptr;
    static cudaEvent_t evRoot = nullptr, ev1 = nullptr, ev2 = nullptr;
    static cudaEvent_t evRouter = nullptr, evReduce = nullptr;
    if (!s1) {
        cudaStreamCreateWithFlags(&s1, cudaStreamNonBlocking);
        cudaStreamCreateWithFlags(&s2, cudaStreamNonBlocking);
        cudaEventCreateWithFlags(&evRoot,   cudaEventDisableTiming);
        cudaEventCreateWithFlags(&ev1,      cudaEventDisableTiming);
        cudaEventCreateWithFlags(&ev2,      cudaEventDisableTiming);
        cudaEventCreateWithFlags(&evRouter, cudaEventDisableTiming);
        cudaEventCreateWithFlags(&evReduce, cudaEventDisableTiming);
    }

    cudaMemsetAsync(p_counts, 0, 2 * NEXP * sizeof(int));

    // fork: transposes on side streams, concurrent with router/scatter
    cudaEventRecord(evRoot, 0);
    cudaStreamWaitEvent(s1, evRoot, 0);
    cudaStreamWaitEvent(s2, evRoot, 0);
    transpose_w1_split<<<dim3(16384 / 32, 1024 / 32), dim3(32, 8), 0, s1>>>(w1);
    cudaEventRecord(ev1, s1);
    transpose_w2_split<<<dim3(1024 / 32, 2048 / 32, NEXP), dim3(32, 8), 0, s2>>>(w2);
    cudaEventRecord(ev2, s2);

    // main chain
    router_kernel<<<TOKENS / 8, 256>>>(x, rw);
    cudaEventRecord(evRouter, 0);
    scatter_gather<<<TOKENS, 128>>>(x);

    // aux-loss reduction concurrent with GEMMs (depends only on router outputs)
    cudaStreamWaitEvent(s1, evRouter, 0);
    reduce_kernel<<<1, 256, 0, s1>>>(out, out_size);
    cudaEventRecord(evReduce, s1);

    cudaStreamWaitEvent(0, ev1, 0);   // gemm1 needs w1 planes
    gemm_bf16<true><<<dim3(DFFN / BN, ROW_TILES), 256, SMEM_SZ>>>(
        (const __nv_bfloat16*)p_xh, (const __nv_bfloat16*)p_xl,
        (const __nv_bfloat16*)p_w1h, (const __nv_bfloat16*)p_w1l);

    cudaStreamWaitEvent(0, ev2, 0);   // gemm2 needs w2 planes
    gemm_bf16<false><<<dim3(DMODEL / BN, ROW_TILES), 256, SMEM_SZ>>>(
        (const __nv_bfloat16*)p_hh, (const __nv_bfloat16*)p_hl,
        (const __nv_bfloat16*)p_w2h, (const __nv_bfloat16*)p_w2l);

    combine_kernel<<<TOKENS, 128>>>(out);
    cudaStreamWaitEvent(0, evReduce, 0);   // join: reduce wrote the out tail
}